// round 3
// baseline (speedup 1.0000x reference)
#include <cuda_runtime.h>
#include <math.h>

// Problem constants (fixed shapes)
#define N_PIX   131072          // 32 * 64 * 64
#define K_CODE  1024
#define D_DIM   64
#define N_ELEM  8388608         // 32 * 64 * 64 * 64 (full NCHW tensor)

// Output layout offsets (flattened tuple, float32) — total 8651778
#define QUANT_OFF 0
#define LOSS_OFF  8388608
#define PERP_OFF  8388609
#define IDX_OFF   8388610
#define NCS_OFF   8519682
#define NEMA_OFF  8520706
#define NEMB_OFF  8586242

// Scratch (device globals; no allocation allowed)
__device__ int   g_idx[N_PIX];
__device__ float g_embT[D_DIM * K_CODE];   // embT[d][k]
__device__ float g_esq[K_CODE];
__device__ float g_counts[K_CODE];
__device__ float g_dw[K_CODE * D_DIM];
__device__ float g_loss;

// ---------------------------------------------------------------------------
// Kernel 1: transpose embed -> embT, compute ||e_k||^2, zero accumulators
// ---------------------------------------------------------------------------
__global__ void prep_kernel(const float* __restrict__ embed) {
    int k = blockIdx.x;
    int t = threadIdx.x;
    float v = embed[k * 64 + t];
    g_embT[t * 1024 + k] = v;
    g_dw[k * 64 + t] = 0.0f;
    float s = v * v;
    #pragma unroll
    for (int o = 16; o; o >>= 1) s += __shfl_down_sync(0xffffffffu, s, o);
    __shared__ float sm[2];
    if ((t & 31) == 0) sm[t >> 5] = s;
    __syncthreads();
    if (t == 0) {
        g_esq[k] = sm[0] + sm[1];
        g_counts[k] = 0.0f;
        if (k == 0) g_loss = 0.0f;
    }
}

// ---------------------------------------------------------------------------
// Kernel 2: argmin GEMM. Block = 128 pixels, codes chunked by 64 through smem.
// 256 threads, 4x8 register tiles. Static smem = 48KB exactly.
// Tracks s = x.e - 0.5*||e||^2 ; argmin dist == argmax s.
// ---------------------------------------------------------------------------
__global__ void __launch_bounds__(256) argmin_kernel(const float* __restrict__ in,
                                                     float* __restrict__ out) {
    __shared__ float4 xs4[2048];   // xs[d][p]: index d*32 + p/4   (32 KB)
    __shared__ float4 es4[1024];   // es[d][k]: index d*16 + k/4   (16 KB)

    const int tid = threadIdx.x;
    const int tx  = tid & 7;       // code group: 8 codes
    const int ty  = tid >> 3;      // pixel group: 4 pixels (0..31)
    const int p0  = blockIdx.x * 128;
    const int bimg = p0 >> 12;     // image (4096 pixels each)
    const int hw0  = p0 & 4095;

    // Load pixel tile: xs[c][p] = in[bimg][c][hw0+p], fully coalesced float4
    const float4* in4 = (const float4*)(in + (size_t)bimg * 262144 + hw0);
    #pragma unroll
    for (int t = 0; t < 8; t++) {
        int i = tid + t * 256;            // 0..2047
        int c = i >> 5, p4 = i & 31;
        xs4[i] = in4[c * 1024 + p4];
    }

    float bestv[4];
    int   besti[4];
    #pragma unroll
    for (int i = 0; i < 4; i++) { bestv[i] = -3.4e38f; besti[i] = 0; }

    const float4* embT4 = (const float4*)g_embT;
    const float4* esq4  = (const float4*)g_esq;

    for (int ck = 0; ck < 16; ck++) {
        __syncthreads();   // protect prior-chunk es reads (and initial xs fill)
        #pragma unroll
        for (int t = 0; t < 4; t++) {
            int i = tid + t * 256;        // 0..1023
            int d = i >> 4, k4 = i & 15;
            es4[i] = embT4[d * 256 + ck * 16 + k4];   // L2-resident embT
        }
        __syncthreads();

        // acc init = -0.5 * ||e||^2 for this thread's 8 codes
        float4 e0 = esq4[ck * 16 + tx * 2];
        float4 e1 = esq4[ck * 16 + tx * 2 + 1];
        float acc[4][8];
        #pragma unroll
        for (int i = 0; i < 4; i++) {
            acc[i][0] = -0.5f * e0.x; acc[i][1] = -0.5f * e0.y;
            acc[i][2] = -0.5f * e0.z; acc[i][3] = -0.5f * e0.w;
            acc[i][4] = -0.5f * e1.x; acc[i][5] = -0.5f * e1.y;
            acc[i][6] = -0.5f * e1.z; acc[i][7] = -0.5f * e1.w;
        }

        #pragma unroll 8
        for (int d = 0; d < 64; d++) {
            float4 av = xs4[d * 32 + ty];                 // pixels ty*4..+3
            float4 b0 = es4[d * 16 + tx * 2];             // codes tx*8..+3
            float4 b1 = es4[d * 16 + tx * 2 + 1];         // codes tx*8+4..+7
            float a[4] = {av.x, av.y, av.z, av.w};
            float b[8] = {b0.x, b0.y, b0.z, b0.w, b1.x, b1.y, b1.z, b1.w};
            #pragma unroll
            for (int i = 0; i < 4; i++)
                #pragma unroll
                for (int j = 0; j < 8; j++)
                    acc[i][j] = fmaf(a[i], b[j], acc[i][j]);
        }

        // running argmax (codes visited in increasing k; strict > keeps lowest)
        #pragma unroll
        for (int j = 0; j < 8; j++) {
            int kg = ck * 64 + tx * 8 + j;
            #pragma unroll
            for (int i = 0; i < 4; i++) {
                if (acc[i][j] > bestv[i]) { bestv[i] = acc[i][j]; besti[i] = kg; }
            }
        }
    }

    // Reduce across the 8 code-group lanes (consecutive tids, same warp)
    #pragma unroll
    for (int i = 0; i < 4; i++) {
        float v = bestv[i];
        int   ix = besti[i];
        #pragma unroll
        for (int o = 4; o; o >>= 1) {
            float v2 = __shfl_xor_sync(0xffffffffu, v, o);
            int   i2 = __shfl_xor_sync(0xffffffffu, ix, o);
            if (v2 > v || (v2 == v && i2 < ix)) { v = v2; ix = i2; }
        }
        if (tx == 0) {
            int n = p0 + ty * 4 + i;
            g_idx[n] = ix;
            out[IDX_OFF + n] = (float)ix;
        }
    }
}

// ---------------------------------------------------------------------------
// Kernel 3: quantize (gather), loss partial, EMA scatter-add
// one thread per NCHW element
// ---------------------------------------------------------------------------
__global__ void quant_kernel(const float* __restrict__ in, float* __restrict__ out) {
    int e = blockIdx.x * 256 + threadIdx.x;
    int b   = e >> 18;          // 64*4096 elements per image
    int rem = e & 262143;
    int c   = rem >> 12;
    int hw  = rem & 4095;
    int n = b * 4096 + hw;
    int r = g_idx[n];

    float q = g_embT[c * 1024 + r];       // embed[r][c]
    float x = in[e];
    out[QUANT_OFF + e] = q;               // quant_st == quantized numerically
    float d = q - x;
    float s = d * d;

    atomicAdd(&g_dw[r * 64 + c], x);
    if (c == 0) atomicAdd(&g_counts[r], 1.0f);

    #pragma unroll
    for (int o = 16; o; o >>= 1) s += __shfl_down_sync(0xffffffffu, s, o);
    __shared__ float sm[8];
    if ((threadIdx.x & 31) == 0) sm[threadIdx.x >> 5] = s;
    __syncthreads();
    if (threadIdx.x == 0) {
        float tot = 0.0f;
        #pragma unroll
        for (int i = 0; i < 8; i++) tot += sm[i];
        atomicAdd(&g_loss, tot);
    }
}

// ---------------------------------------------------------------------------
// Kernel 4: EMA finalize, perplexity, loss. 1 block x 1024 threads.
// ---------------------------------------------------------------------------
__global__ void finalize_kernel(const float* __restrict__ ema_cs,
                                const float* __restrict__ ema_w,
                                float* __restrict__ out) {
    __shared__ float s1[1024];
    __shared__ float s2[1024];
    __shared__ float scl[1024];
    int k = threadIdx.x;

    float cnt = g_counts[k];
    float ncs = 0.99f * ema_cs[k] + 0.01f * cnt;
    out[NCS_OFF + k] = ncs;

    float p = cnt * (1.0f / 131072.0f);
    s1[k] = ncs;
    s2[k] = p * logf(p + 1e-10f);
    __syncthreads();
    for (int o = 512; o; o >>= 1) {
        if (k < o) { s1[k] += s1[k + o]; s2[k] += s2[k + o]; }
        __syncthreads();
    }
    float nsum = s1[0];
    float csz = (ncs + 1e-5f) / (nsum + 1024.0f * 1e-5f) * nsum;
    csz = fmaxf(csz, 1e-5f);
    scl[k] = csz;
    __syncthreads();

    #pragma unroll
    for (int it = 0; it < 64; it++) {
        int e = it * 1024 + k;            // coalesced over (code, dim)
        int kk = e >> 6;
        float w = 0.99f * ema_w[e] + 0.01f * g_dw[e];
        out[NEMA_OFF + e] = w;
        out[NEMB_OFF + e] = w / scl[kk];
    }

    if (k == 0) {
        out[LOSS_OFF] = 0.25f * g_loss * (1.0f / 8388608.0f);
        out[PERP_OFF] = expf(-s2[0]);
    }
}

// ---------------------------------------------------------------------------
extern "C" void kernel_launch(void* const* d_in, const int* in_sizes, int n_in,
                              void* d_out, int out_size) {
    const float* in    = (const float*)d_in[0];   // [32,64,64,64] NCHW
    const float* embed = (const float*)d_in[1];   // [1024,64]
    const float* ecs   = (const float*)d_in[2];   // [1024]
    const float* emw   = (const float*)d_in[3];   // [1024,64]
    float* out = (float*)d_out;

    prep_kernel<<<1024, 64>>>(embed);
    argmin_kernel<<<1024, 256>>>(in, out);
    quant_kernel<<<32768, 256>>>(in, out);
    finalize_kernel<<<1, 1024>>>(ecs, emw, out);
}

// round 4
// speedup vs baseline: 1.6846x; 1.6846x over previous
#include <cuda_runtime.h>
#include <math.h>

// Problem constants (fixed shapes)
#define N_PIX   131072          // 32 * 64 * 64
#define K_CODE  1024
#define D_DIM   64
#define N_ELEM  8388608         // 32*64*64*64 (full NCHW tensor)

// Output layout offsets (flattened tuple, float32) — total 8651778
#define QUANT_OFF 0
#define LOSS_OFF  8388608
#define PERP_OFF  8388609
#define IDX_OFF   8388610
#define NCS_OFF   8519682
#define NEMA_OFF  8520706
#define NEMB_OFF  8586242

// Scratch (device globals; no allocation allowed)
__device__ int   g_idx[N_PIX];
__device__ float g_embT[D_DIM * K_CODE];   // embT[d][k]
__device__ float g_esq[K_CODE];
__device__ float g_counts[K_CODE];
__device__ float g_dw[K_CODE * D_DIM];
__device__ float g_scl[K_CODE];
__device__ float g_loss;

// ---------------------------------------------------------------------------
// Kernel 1: transpose embed -> embT, ||e_k||^2, zero accumulators
// ---------------------------------------------------------------------------
__global__ void prep_kernel(const float* __restrict__ embed) {
    int k = blockIdx.x;
    int t = threadIdx.x;
    float v = embed[k * 64 + t];
    g_embT[t * 1024 + k] = v;
    g_dw[k * 64 + t] = 0.0f;
    float s = v * v;
    #pragma unroll
    for (int o = 16; o; o >>= 1) s += __shfl_down_sync(0xffffffffu, s, o);
    __shared__ float sm[2];
    if ((t & 31) == 0) sm[t >> 5] = s;
    __syncthreads();
    if (t == 0) {
        g_esq[k] = sm[0] + sm[1];
        g_counts[k] = 0.0f;
        if (k == 0) g_loss = 0.0f;
    }
}

// ---------------------------------------------------------------------------
// Kernel 2 (primary): argmin GEMM. Block = 256 pixels, 64-code chunks in smem.
// 256 threads, 8x8 register tile. Dynamic smem 80KB, 2 blocks/SM.
// Tracks s = x.e - 0.5*||e||^2 ; argmin dist == argmax s.
// ---------------------------------------------------------------------------
#define ARGMIN_SMEM (80 * 1024)
__global__ void __launch_bounds__(256, 2) argmin_dyn(const float* __restrict__ in,
                                                     float* __restrict__ out) {
    extern __shared__ float4 sh4[];
    float4* xs4 = sh4;            // xs[d][p]: d*64 + p/4  (4096 float4, 64KB)
    float4* es4 = sh4 + 4096;     // es[d][k]: d*16 + k/4  (1024 float4, 16KB)

    const int tid = threadIdx.x;
    const int tx  = tid & 7;      // code group: 8 codes
    const int ty  = tid >> 3;     // pixel group: 8 pixels (0..31)
    const int p0  = blockIdx.x * 256;
    const int bimg = p0 >> 12;
    const int hw0  = p0 & 4095;

    // Load pixel tile: xs[c][p] = in[bimg][c][hw0+p], fully coalesced float4
    const float4* in4 = (const float4*)(in + (size_t)bimg * 262144 + hw0);
    #pragma unroll
    for (int t = 0; t < 16; t++) {
        int i = tid + t * 256;            // 0..4095
        int c = i >> 6, p4 = i & 63;
        xs4[i] = in4[c * 1024 + p4];
    }

    float bestv[8];
    int   besti[8];
    #pragma unroll
    for (int i = 0; i < 8; i++) { bestv[i] = -3.4e38f; besti[i] = 0; }

    const float4* embT4 = (const float4*)g_embT;
    const float4* esq4  = (const float4*)g_esq;

    for (int ck = 0; ck < 16; ck++) {
        __syncthreads();
        #pragma unroll
        for (int t = 0; t < 4; t++) {
            int i = tid + t * 256;        // 0..1023
            int d = i >> 4, k4 = i & 15;
            es4[i] = embT4[d * 256 + ck * 16 + k4];
        }
        __syncthreads();

        float4 e0 = esq4[ck * 16 + tx * 2];
        float4 e1 = esq4[ck * 16 + tx * 2 + 1];
        float acc[8][8];
        #pragma unroll
        for (int i = 0; i < 8; i++) {
            acc[i][0] = -0.5f * e0.x; acc[i][1] = -0.5f * e0.y;
            acc[i][2] = -0.5f * e0.z; acc[i][3] = -0.5f * e0.w;
            acc[i][4] = -0.5f * e1.x; acc[i][5] = -0.5f * e1.y;
            acc[i][6] = -0.5f * e1.z; acc[i][7] = -0.5f * e1.w;
        }

        #pragma unroll 4
        for (int d = 0; d < 64; d++) {
            float4 a0 = xs4[d * 64 + ty * 2];
            float4 a1 = xs4[d * 64 + ty * 2 + 1];
            float4 b0 = es4[d * 16 + tx * 2];
            float4 b1 = es4[d * 16 + tx * 2 + 1];
            float a[8] = {a0.x, a0.y, a0.z, a0.w, a1.x, a1.y, a1.z, a1.w};
            float b[8] = {b0.x, b0.y, b0.z, b0.w, b1.x, b1.y, b1.z, b1.w};
            #pragma unroll
            for (int i = 0; i < 8; i++)
                #pragma unroll
                for (int j = 0; j < 8; j++)
                    acc[i][j] = fmaf(a[i], b[j], acc[i][j]);
        }

        #pragma unroll
        for (int j = 0; j < 8; j++) {
            int kg = ck * 64 + tx * 8 + j;
            #pragma unroll
            for (int i = 0; i < 8; i++) {
                if (acc[i][j] > bestv[i]) { bestv[i] = acc[i][j]; besti[i] = kg; }
            }
        }
    }

    // Reduce across the 8 code-group lanes (consecutive tids, same warp)
    #pragma unroll
    for (int i = 0; i < 8; i++) {
        float v = bestv[i];
        int   ix = besti[i];
        #pragma unroll
        for (int o = 4; o; o >>= 1) {
            float v2 = __shfl_xor_sync(0xffffffffu, v, o);
            int   i2 = __shfl_xor_sync(0xffffffffu, ix, o);
            if (v2 > v || (v2 == v && i2 < ix)) { v = v2; ix = i2; }
        }
        if (tx == 0) {
            int n = p0 + ty * 8 + i;
            g_idx[n] = ix;
            out[IDX_OFF + n] = (float)ix;
        }
    }
}

// ---------------------------------------------------------------------------
// Kernel 2 (fallback): proven 48KB-static version, 128 pixels/block
// ---------------------------------------------------------------------------
__global__ void __launch_bounds__(256) argmin_static(const float* __restrict__ in,
                                                     float* __restrict__ out) {
    __shared__ float4 xs4[2048];
    __shared__ float4 es4[1024];

    const int tid = threadIdx.x;
    const int tx  = tid & 7;
    const int ty  = tid >> 3;
    const int p0  = blockIdx.x * 128;
    const int bimg = p0 >> 12;
    const int hw0  = p0 & 4095;

    const float4* in4 = (const float4*)(in + (size_t)bimg * 262144 + hw0);
    #pragma unroll
    for (int t = 0; t < 8; t++) {
        int i = tid + t * 256;
        int c = i >> 5, p4 = i & 31;
        xs4[i] = in4[c * 1024 + p4];
    }

    float bestv[4];
    int   besti[4];
    #pragma unroll
    for (int i = 0; i < 4; i++) { bestv[i] = -3.4e38f; besti[i] = 0; }

    const float4* embT4 = (const float4*)g_embT;
    const float4* esq4  = (const float4*)g_esq;

    for (int ck = 0; ck < 16; ck++) {
        __syncthreads();
        #pragma unroll
        for (int t = 0; t < 4; t++) {
            int i = tid + t * 256;
            int d = i >> 4, k4 = i & 15;
            es4[i] = embT4[d * 256 + ck * 16 + k4];
        }
        __syncthreads();

        float4 e0 = esq4[ck * 16 + tx * 2];
        float4 e1 = esq4[ck * 16 + tx * 2 + 1];
        float acc[4][8];
        #pragma unroll
        for (int i = 0; i < 4; i++) {
            acc[i][0] = -0.5f * e0.x; acc[i][1] = -0.5f * e0.y;
            acc[i][2] = -0.5f * e0.z; acc[i][3] = -0.5f * e0.w;
            acc[i][4] = -0.5f * e1.x; acc[i][5] = -0.5f * e1.y;
            acc[i][6] = -0.5f * e1.z; acc[i][7] = -0.5f * e1.w;
        }

        #pragma unroll 8
        for (int d = 0; d < 64; d++) {
            float4 av = xs4[d * 32 + ty];
            float4 b0 = es4[d * 16 + tx * 2];
            float4 b1 = es4[d * 16 + tx * 2 + 1];
            float a[4] = {av.x, av.y, av.z, av.w};
            float b[8] = {b0.x, b0.y, b0.z, b0.w, b1.x, b1.y, b1.z, b1.w};
            #pragma unroll
            for (int i = 0; i < 4; i++)
                #pragma unroll
                for (int j = 0; j < 8; j++)
                    acc[i][j] = fmaf(a[i], b[j], acc[i][j]);
        }

        #pragma unroll
        for (int j = 0; j < 8; j++) {
            int kg = ck * 64 + tx * 8 + j;
            #pragma unroll
            for (int i = 0; i < 4; i++) {
                if (acc[i][j] > bestv[i]) { bestv[i] = acc[i][j]; besti[i] = kg; }
            }
        }
    }

    #pragma unroll
    for (int i = 0; i < 4; i++) {
        float v = bestv[i];
        int   ix = besti[i];
        #pragma unroll
        for (int o = 4; o; o >>= 1) {
            float v2 = __shfl_xor_sync(0xffffffffu, v, o);
            int   i2 = __shfl_xor_sync(0xffffffffu, ix, o);
            if (v2 > v || (v2 == v && i2 < ix)) { v = v2; ix = i2; }
        }
        if (tx == 0) {
            int n = p0 + ty * 4 + i;
            g_idx[n] = ix;
            out[IDX_OFF + n] = (float)ix;
        }
    }
}

// ---------------------------------------------------------------------------
// Kernel 3: quantize (gather), loss partial, EMA scatter-add
// ---------------------------------------------------------------------------
__global__ void quant_kernel(const float* __restrict__ in, float* __restrict__ out) {
    int e = blockIdx.x * 256 + threadIdx.x;
    int b   = e >> 18;
    int rem = e & 262143;
    int c   = rem >> 12;
    int hw  = rem & 4095;
    int n = b * 4096 + hw;
    int r = g_idx[n];

    float q = g_embT[c * 1024 + r];
    float x = in[e];
    out[QUANT_OFF + e] = q;
    float d = q - x;
    float s = d * d;

    atomicAdd(&g_dw[r * 64 + c], x);
    if (c == 0) atomicAdd(&g_counts[r], 1.0f);

    #pragma unroll
    for (int o = 16; o; o >>= 1) s += __shfl_down_sync(0xffffffffu, s, o);
    __shared__ float sm[8];
    if ((threadIdx.x & 31) == 0) sm[threadIdx.x >> 5] = s;
    __syncthreads();
    if (threadIdx.x == 0) {
        float tot = 0.0f;
        #pragma unroll
        for (int i = 0; i < 8; i++) tot += sm[i];
        atomicAdd(&g_loss, tot);
    }
}

// ---------------------------------------------------------------------------
// Kernel 4a: scalars — new_cluster_size, perplexity, loss, scale factors
// ---------------------------------------------------------------------------
__global__ void scalar_kernel(const float* __restrict__ ema_cs,
                              float* __restrict__ out) {
    __shared__ float s1[1024];
    __shared__ float s2[1024];
    int k = threadIdx.x;

    float cnt = g_counts[k];
    float ncs = 0.99f * ema_cs[k] + 0.01f * cnt;
    out[NCS_OFF + k] = ncs;

    float p = cnt * (1.0f / 131072.0f);
    s1[k] = ncs;
    s2[k] = p * logf(p + 1e-10f);
    __syncthreads();
    for (int o = 512; o; o >>= 1) {
        if (k < o) { s1[k] += s1[k + o]; s2[k] += s2[k + o]; }
        __syncthreads();
    }
    float nsum = s1[0];
    float csz = (ncs + 1e-5f) / (nsum + 1024.0f * 1e-5f) * nsum;
    g_scl[k] = fmaxf(csz, 1e-5f);

    if (k == 0) {
        out[LOSS_OFF] = 0.25f * g_loss * (1.0f / 8388608.0f);
        out[PERP_OFF] = expf(-s2[0]);
    }
}

// ---------------------------------------------------------------------------
// Kernel 4b: wide EMA-w / new-embed update (65536 elems across the chip)
// ---------------------------------------------------------------------------
__global__ void ema_kernel(const float* __restrict__ ema_w,
                           float* __restrict__ out) {
    int e = blockIdx.x * 512 + threadIdx.x;   // 0..65535
    int kk = e >> 6;
    float w = 0.99f * ema_w[e] + 0.01f * g_dw[e];
    out[NEMA_OFF + e] = w;
    out[NEMB_OFF + e] = w / g_scl[kk];
}

// ---------------------------------------------------------------------------
extern "C" void kernel_launch(void* const* d_in, const int* in_sizes, int n_in,
                              void* d_out, int out_size) {
    const float* in    = (const float*)d_in[0];
    const float* embed = (const float*)d_in[1];
    const float* ecs   = (const float*)d_in[2];
    const float* emw   = (const float*)d_in[3];
    float* out = (float*)d_out;

    prep_kernel<<<1024, 64>>>(embed);

    cudaError_t attr_ok = cudaFuncSetAttribute(
        argmin_dyn, cudaFuncAttributeMaxDynamicSharedMemorySize, ARGMIN_SMEM);
    if (attr_ok == cudaSuccess) {
        argmin_dyn<<<512, 256, ARGMIN_SMEM>>>(in, out);
    } else {
        argmin_static<<<1024, 256>>>(in, out);
    }

    quant_kernel<<<32768, 256>>>(in, out);
    scalar_kernel<<<1, 1024>>>(ecs, out);
    ema_kernel<<<128, 512>>>(emw, out);
}